// round 2
// baseline (speedup 1.0000x reference)
#include <cuda_runtime.h>
#include <cuda_fp16.h>
#include <cstdint>

// ============================================================================
// CATSCluster fused kernel — sm_103 baseline-PTX tensor path.
// (tcgen05 is unavailable: harness compiles via compute_103 virtual arch.)
//
//   X = X_data[:, 1:, :]  (16 x 4096 x 2304 fp32)
//   p1 = X[.., 768:1536] -> relu(relu(p1@W1^T)@W2^T) = Ha2   (128)
//   p2 = X[..,1536:2304] -> same weights             = Hb2
//   q  = X[..,   0: 768] -> relu(relu(q @W3^T)@W4^T) = Hq2
//   out = tanh(relu( (Hq2 * |Ha2-Hb2|) @ W5^T ))
//
// Block = 128 rows, 256 threads (8 warps).
// L1 GEMM (M=128,N=256,K=768): warp tile 64m x 64n, k-chunks of 64,
//   A fp32->fp16 staged in smem (pad-144B rows, conflict-free ldmatrix),
//   B pre-packed in fragment order by prep kernel, staged via cp.async.
// L2 GEMM (M=128,N=128,K=256): H1 relu'd to smem (pad-528B rows), warp
//   tile 32m x 64n, B (W2/W4) fragment-packed + staged once per slice.
// Combine kept in smem D buffer; final W5 dot + quad-shfl reduce.
// ============================================================================

// ---- smem layout (bytes) ----
static constexpr int SM_W5   = 0;                      // 512 B
static constexpr int SM_PART = 512;                    // float[128][2]
static constexpr int SM_A    = 2048;                   // 128 x 144 B
static constexpr int SM_B    = SM_A + 128 * 144;       // 32 KB (L1 B frag chunk)
static constexpr int SM_H1   = SM_B + 32768;           // 128 x 528 B
static constexpr int SM_W2   = SM_H1 + 128 * 528;      // 64 KB (L2 B frags)
static constexpr int SM_D    = SM_W2 + 65536;          // 128 x 272 B
static constexpr int SMEM_BYTES = SM_D + 128 * 272;    // 221184 B

// Fragment-packed fp16 weights (prep kernel fills these every launch).
// L1: [chunk 12][n8-tile 32][k16 4][lane 32][4 halves]
// L2: [n8-tile 16][k16 16][lane 32][4 halves]
__device__ __half g_B1[2][12 * 32 * 4 * 32 * 4];   // W1, W3  (196608 halves each)
__device__ __half g_B2[2][16 * 16 * 32 * 4];       // W2, W4  (32768 halves each)

// ---------------------------------------------------------------- helpers
__device__ __forceinline__ uint32_t smem_u32(const void* p) {
    return (uint32_t)__cvta_generic_to_shared(p);
}
__device__ __forceinline__ void ldm_x4(uint32_t r[4], uint32_t addr) {
    asm volatile("ldmatrix.sync.aligned.m8n8.x4.shared.b16 {%0,%1,%2,%3}, [%4];"
                 : "=r"(r[0]), "=r"(r[1]), "=r"(r[2]), "=r"(r[3]) : "r"(addr));
}
__device__ __forceinline__ void mma16816(float c[4], const uint32_t a[4],
                                         uint32_t b0, uint32_t b1) {
    asm volatile(
        "mma.sync.aligned.m16n8k16.row.col.f32.f16.f16.f32 "
        "{%0,%1,%2,%3}, {%4,%5,%6,%7}, {%8,%9}, {%0,%1,%2,%3};"
        : "+f"(c[0]), "+f"(c[1]), "+f"(c[2]), "+f"(c[3])
        : "r"(a[0]), "r"(a[1]), "r"(a[2]), "r"(a[3]), "r"(b0), "r"(b1));
}
__device__ __forceinline__ void cp_async16(uint32_t saddr, const void* gaddr) {
    asm volatile("cp.async.cg.shared.global [%0], [%1], 16;"
                 :: "r"(saddr), "l"(gaddr) : "memory");
}
__device__ __forceinline__ void cp_async_wait_all() {
    asm volatile("cp.async.commit_group;\n\tcp.async.wait_group 0;" ::: "memory");
}
__device__ __forceinline__ uint32_t h2u(__half2 h) {
    return *reinterpret_cast<uint32_t*>(&h);
}

// ------------------------------------------------- weight frag-pack kernel
__global__ void prep_kernel(const float* __restrict__ W1, const float* __restrict__ W2,
                            const float* __restrict__ W3, const float* __restrict__ W4) {
    int e = blockIdx.x * blockDim.x + threadIdx.x;    // 0 .. 196607
    {
        // L1 weights: W[n(256)][k(768)]
        int n = e / 768, k = e % 768;
        int kc = k >> 6;                // 64-k chunk
        int j  = (k >> 4) & 3;          // k16 tile within chunk
        int kl = k & 15;                // k within tile
        int p  = kl >> 3;               // which b-reg
        int pos = kl & 7;
        int lane = (n & 7) * 4 + (pos >> 1);
        int h = pos & 1;
        int idx = ((((kc * 32 + (n >> 3)) * 4 + j) * 32 + lane) << 2) + p * 2 + h;
        g_B1[0][idx] = __float2half_rn(W1[e]);
        g_B1[1][idx] = __float2half_rn(W3[e]);
    }
    if (e < 128 * 256) {
        // L2 weights: W[n(128)][k(256)]
        int n = e / 256, k = e % 256;
        int j  = k >> 4;
        int kl = k & 15;
        int p  = kl >> 3;
        int pos = kl & 7;
        int lane = (n & 7) * 4 + (pos >> 1);
        int h = pos & 1;
        int idx = ((((n >> 3) * 16 + j) * 32 + lane) << 2) + p * 2 + h;
        g_B2[0][idx] = __float2half_rn(W2[e]);
        g_B2[1][idx] = __float2half_rn(W4[e]);
    }
}

// ----------------------------------------------------------------- main kernel
__global__ void __launch_bounds__(256, 1) fused_kernel(
    const float* __restrict__ X, const float* __restrict__ W5, float* __restrict__ out) {
    extern __shared__ __align__(128) char smem[];
    const uint32_t sb = smem_u32(smem);
    const int tid = threadIdx.x;
    const int w   = tid >> 5;           // warp 0..7
    const int l   = tid & 31;
    const int lq  = l & 3;              // quad lane

    if (tid < 128) ((float*)(smem + SM_W5))[tid] = W5[tid];

    const long long blk = blockIdx.x;
    const float* Xbase = X + ((blk >> 5) * 4097LL + (blk & 31) * 128LL + 1LL) * 2304LL;

    // L1 warp tile: 64m x 64n.  wm = m-half, wq = n-quarter.
    const int wm = w >> 2, wq = w & 3;
    // L2 warp tile: 32m x 64n.  wm2 = m-quarter, wn2 = n-half.
    const int wm2 = w >> 1, wn2 = w & 1;

    const float* W5s = (const float*)(smem + SM_W5);
    float* parts = (float*)(smem + SM_PART);

    for (int s = 0; s < 3; s++) {
        const int soff = (s == 0) ? 768 : (s == 1) ? 1536 : 0;   // p1, p2, q
        const __half* B1g = g_B1[s == 2 ? 1 : 0];
        const __half* B2g = g_B2[s == 2 ? 1 : 0];

        // ================= layer 1: acc[4 mf][8 t][4] = X @ W^T =================
        float acc[4][8][4];
        #pragma unroll
        for (int a = 0; a < 4; a++)
            #pragma unroll
            for (int b = 0; b < 8; b++)
                #pragma unroll
                for (int c = 0; c < 4; c++) acc[a][b][c] = 0.f;

        for (int kc = 0; kc < 12; kc++) {
            __syncthreads();
            // ---- stage A: 128 rows x 64 f32 -> f16, pad-144B rows ----
            {
                const int row = tid >> 1, half = tid & 1;
                const float4* src = (const float4*)(Xbase + (long long)row * 2304
                                                    + soff + kc * 64 + half * 32);
                uint32_t dst = sb + SM_A + row * 144 + half * 64;
                #pragma unroll
                for (int i = 0; i < 4; i++) {
                    float4 v0 = src[2 * i], v1 = src[2 * i + 1];
                    uint4 pk;
                    pk.x = h2u(__floats2half2_rn(v0.x, v0.y));
                    pk.y = h2u(__floats2half2_rn(v0.z, v0.w));
                    pk.z = h2u(__floats2half2_rn(v1.x, v1.y));
                    pk.w = h2u(__floats2half2_rn(v1.z, v1.w));
                    asm volatile("st.shared.v4.b32 [%0], {%1,%2,%3,%4};"
                                 :: "r"(dst + i * 16), "r"(pk.x), "r"(pk.y), "r"(pk.z), "r"(pk.w));
                }
            }
            // ---- stage B: 32 KB frag-packed chunk via cp.async ----
            {
                const char* src = (const char*)(B1g + kc * 16384) + tid * 16;
                uint32_t dst = sb + SM_B + tid * 16;
                #pragma unroll
                for (int i = 0; i < 8; i++)
                    cp_async16(dst + i * 4096, src + i * 4096);
            }
            // ---- stage W2 frags once per weight change (overlap with kc==0) ----
            if (kc == 0 && s != 1) {
                const char* src = (const char*)B2g + tid * 16;
                uint32_t dst = sb + SM_W2 + tid * 16;
                #pragma unroll
                for (int i = 0; i < 16; i++)
                    cp_async16(dst + i * 4096, src + i * 4096);
            }
            cp_async_wait_all();
            __syncthreads();

            // ---- compute: 4 k16 steps x (4 A frags, 8 B frags, 32 mma) ----
            const uint32_t aBase = sb + SM_A + (wm * 64 + (l & 15)) * 144 + ((l >> 4) * 8) * 2;
            const uint2* bBase = (const uint2*)(smem + SM_B) + (wq * 8) * 4 * 32 + l;
            #pragma unroll
            for (int j = 0; j < 4; j++) {
                uint32_t afr[4][4];
                #pragma unroll
                for (int mf = 0; mf < 4; mf++)
                    ldm_x4(afr[mf], aBase + mf * 16 * 144 + j * 32);
                uint32_t bfr[8][2];
                #pragma unroll
                for (int t = 0; t < 8; t++) {
                    uint2 bv = bBase[(t * 4 + j) * 32];
                    bfr[t][0] = bv.x; bfr[t][1] = bv.y;
                }
                #pragma unroll
                for (int mf = 0; mf < 4; mf++)
                    #pragma unroll
                    for (int t = 0; t < 8; t++)
                        mma16816(acc[mf][t], afr[mf], bfr[t][0], bfr[t][1]);
            }
        }

        // ================= relu -> fp16 -> H1 smem (pad-528B rows) =================
        __syncthreads();   // all warps done reading SM_A/SM_B of last chunk
        #pragma unroll
        for (int mf = 0; mf < 4; mf++) {
            #pragma unroll
            for (int t = 0; t < 8; t++) {
                const int r0 = wm * 64 + mf * 16 + (l >> 2);
                const int col = wq * 64 + t * 8 + lq * 2;
                float* c = acc[mf][t];
                *(uint32_t*)(smem + SM_H1 + r0 * 528 + col * 2) =
                    h2u(__floats2half2_rn(fmaxf(c[0], 0.f), fmaxf(c[1], 0.f)));
                *(uint32_t*)(smem + SM_H1 + (r0 + 8) * 528 + col * 2) =
                    h2u(__floats2half2_rn(fmaxf(c[2], 0.f), fmaxf(c[3], 0.f)));
            }
        }
        __syncthreads();

        // ================= layer 2: acc2[2 mf][8 t][4] = H1 @ W2^T =================
        float acc2[2][8][4];
        #pragma unroll
        for (int a = 0; a < 2; a++)
            #pragma unroll
            for (int b = 0; b < 8; b++)
                #pragma unroll
                for (int c = 0; c < 4; c++) acc2[a][b][c] = 0.f;

        {
            const uint32_t aBase = sb + SM_H1 + (wm2 * 32 + (l & 15)) * 528 + ((l >> 4) * 8) * 2;
            const uint2* bBase = (const uint2*)(smem + SM_W2) + (wn2 * 8) * 16 * 32 + l;
            #pragma unroll
            for (int j = 0; j < 16; j++) {
                uint32_t afr[2][4];
                #pragma unroll
                for (int mf = 0; mf < 2; mf++)
                    ldm_x4(afr[mf], aBase + mf * 16 * 528 + j * 32);
                #pragma unroll
                for (int t = 0; t < 8; t++) {
                    uint2 bv = bBase[(t * 16 + j) * 32];
                    #pragma unroll
                    for (int mf = 0; mf < 2; mf++)
                        mma16816(acc2[mf][t], afr[mf], bv.x, bv.y);
                }
            }
        }

        // ================= combine via D buffer (pad-272B rows) =================
        if (s == 0) {
            #pragma unroll
            for (int mf = 0; mf < 2; mf++)
                #pragma unroll
                for (int t = 0; t < 8; t++) {
                    const int r0 = wm2 * 32 + mf * 16 + (l >> 2);
                    const int col = wn2 * 64 + t * 8 + lq * 2;
                    float* c = acc2[mf][t];
                    *(uint32_t*)(smem + SM_D + r0 * 272 + col * 2) =
                        h2u(__floats2half2_rn(fmaxf(c[0], 0.f), fmaxf(c[1], 0.f)));
                    *(uint32_t*)(smem + SM_D + (r0 + 8) * 272 + col * 2) =
                        h2u(__floats2half2_rn(fmaxf(c[2], 0.f), fmaxf(c[3], 0.f)));
                }
        } else if (s == 1) {
            #pragma unroll
            for (int mf = 0; mf < 2; mf++)
                #pragma unroll
                for (int t = 0; t < 8; t++) {
                    const int r0 = wm2 * 32 + mf * 16 + (l >> 2);
                    const int col = wn2 * 64 + t * 8 + lq * 2;
                    float* c = acc2[mf][t];
                    uint32_t* d0 = (uint32_t*)(smem + SM_D + r0 * 272 + col * 2);
                    uint32_t* d1 = (uint32_t*)(smem + SM_D + (r0 + 8) * 272 + col * 2);
                    __half2 ha = *(__half2*)d0;
                    __half2 hb = *(__half2*)d1;
                    float2 fa = __half22float2(ha);
                    float2 fb = __half22float2(hb);
                    *d0 = h2u(__floats2half2_rn(fabsf(fa.x - fmaxf(c[0], 0.f)),
                                                fabsf(fa.y - fmaxf(c[1], 0.f))));
                    *d1 = h2u(__floats2half2_rn(fabsf(fb.x - fmaxf(c[2], 0.f)),
                                                fabsf(fb.y - fmaxf(c[3], 0.f))));
                }
        } else {
            // s==2: dot with W5, quad reduce, write row partials
            float pd[2][2] = {{0.f, 0.f}, {0.f, 0.f}};
            #pragma unroll
            for (int mf = 0; mf < 2; mf++)
                #pragma unroll
                for (int t = 0; t < 8; t++) {
                    const int r0 = wm2 * 32 + mf * 16 + (l >> 2);
                    const int col = wn2 * 64 + t * 8 + lq * 2;
                    float* c = acc2[mf][t];
                    float2 da = __half22float2(*(__half2*)(smem + SM_D + r0 * 272 + col * 2));
                    float2 db = __half22float2(*(__half2*)(smem + SM_D + (r0 + 8) * 272 + col * 2));
                    float w0 = W5s[col], w1 = W5s[col + 1];
                    pd[mf][0] += w0 * fmaxf(c[0], 0.f) * da.x + w1 * fmaxf(c[1], 0.f) * da.y;
                    pd[mf][1] += w0 * fmaxf(c[2], 0.f) * db.x + w1 * fmaxf(c[3], 0.f) * db.y;
                }
            #pragma unroll
            for (int mf = 0; mf < 2; mf++)
                #pragma unroll
                for (int rr = 0; rr < 2; rr++) {
                    float v = pd[mf][rr];
                    v += __shfl_xor_sync(0xFFFFFFFF, v, 1);
                    v += __shfl_xor_sync(0xFFFFFFFF, v, 2);
                    if (lq == 0) {
                        int row = wm2 * 32 + mf * 16 + rr * 8 + (l >> 2);
                        parts[row * 2 + wn2] = v;
                    }
                }
        }
    }

    __syncthreads();
    if (tid < 128) {
        float sum = parts[tid * 2] + parts[tid * 2 + 1];
        out[blk * 128 + tid] = tanhf(fmaxf(sum, 0.f));
    }
}

// ------------------------------------------------------------------- launcher
extern "C" void kernel_launch(void* const* d_in, const int* in_sizes, int n_in,
                              void* d_out, int out_size) {
    const float* X  = (const float*)d_in[0];
    const float* W1 = (const float*)d_in[1];
    const float* W2 = (const float*)d_in[2];
    const float* W3 = (const float*)d_in[3];
    const float* W4 = (const float*)d_in[4];
    const float* W5 = (const float*)d_in[5];
    (void)in_sizes; (void)n_in; (void)out_size;

    cudaFuncSetAttribute(fused_kernel, cudaFuncAttributeMaxDynamicSharedMemorySize, SMEM_BYTES);

    prep_kernel<<<768, 256>>>(W1, W2, W3, W4);
    fused_kernel<<<512, 256, SMEM_BYTES>>>(X, W5, (float*)d_out);
}

// round 3
// speedup vs baseline: 1.7683x; 1.7683x over previous
#include <cuda_runtime.h>
#include <cuda_fp16.h>
#include <cstdint>

// ============================================================================
// CATSCluster fused kernel — sm_103 baseline-PTX tensor path, pipelined.
//
//   X = X_data[:, 1:, :]  (16 x 4096 x 2304 fp32)
//   p1 = X[.., 768:1536] -> relu(relu(p1@W1^T)@W2^T) = Ha2   (128)
//   p2 = X[..,1536:2304] -> same weights             = Hb2
//   q  = X[..,   0: 768] -> relu(relu(q @W3^T)@W4^T) = Hq2
//   out = tanh(relu( (Hq2 * |Ha2-Hb2|) @ W5^T ))
//
// Round-3 changes vs round-2 (653us):
//  * A (X) staged fp32 via double-buffered cp.async; fp32->fp16 convert is
//    smem->smem right before compute -> DRAM fetch of chunk c+1 overlaps
//    MMAs of chunk c. Slice-boundary prefetch overlaps the whole L2-gemm /
//    combine epilogue.
//  * B fragments read directly from global (L2-resident, fragment-packed by
//    prep kernel) with software prefetch across k16 steps -> no B smem
//    buffers, no B staging syncs.
// ============================================================================

// ---- smem layout (bytes) ----
static constexpr int A32_STRIDE = 272;                  // 64 f32 + 16B pad
static constexpr int A32_BYTES  = 128 * A32_STRIDE;     // 34816
static constexpr int SM_W5   = 0;                       // 512 B
static constexpr int SM_PART = 512;                     // float[128][2]
static constexpr int SM_A32  = 2048;                    // 2 x 34816
static constexpr int SM_AF16 = SM_A32 + 2 * A32_BYTES;  // 128 x 144
static constexpr int SM_H1   = SM_AF16 + 128 * 144;     // 128 x 528
static constexpr int SM_D    = SM_H1 + 128 * 528;       // 128 x 272
static constexpr int SMEM_BYTES = SM_D + 128 * 272;     // 192512

// Fragment-packed fp16 weights (prep kernel fills these every launch).
// L1: [chunk 12][n8-tile 32][k16 4][lane 32][4 halves]
// L2: [n8-tile 16][k16 16][lane 32][4 halves]
__device__ __half g_B1[2][12 * 32 * 4 * 32 * 4];   // W1, W3
__device__ __half g_B2[2][16 * 16 * 32 * 4];       // W2, W4

// ---------------------------------------------------------------- helpers
__device__ __forceinline__ uint32_t smem_u32(const void* p) {
    return (uint32_t)__cvta_generic_to_shared(p);
}
__device__ __forceinline__ void ldm_x4(uint32_t r[4], uint32_t addr) {
    asm volatile("ldmatrix.sync.aligned.m8n8.x4.shared.b16 {%0,%1,%2,%3}, [%4];"
                 : "=r"(r[0]), "=r"(r[1]), "=r"(r[2]), "=r"(r[3]) : "r"(addr));
}
__device__ __forceinline__ void mma16816(float c[4], const uint32_t a[4],
                                         uint32_t b0, uint32_t b1) {
    asm volatile(
        "mma.sync.aligned.m16n8k16.row.col.f32.f16.f16.f32 "
        "{%0,%1,%2,%3}, {%4,%5,%6,%7}, {%8,%9}, {%0,%1,%2,%3};"
        : "+f"(c[0]), "+f"(c[1]), "+f"(c[2]), "+f"(c[3])
        : "r"(a[0]), "r"(a[1]), "r"(a[2]), "r"(a[3]), "r"(b0), "r"(b1));
}
__device__ __forceinline__ void cp_async16(uint32_t saddr, const void* gaddr) {
    asm volatile("cp.async.cg.shared.global [%0], [%1], 16;"
                 :: "r"(saddr), "l"(gaddr) : "memory");
}
__device__ __forceinline__ void cp_commit() {
    asm volatile("cp.async.commit_group;" ::: "memory");
}
__device__ __forceinline__ void cp_wait1() {
    asm volatile("cp.async.wait_group 1;" ::: "memory");
}
__device__ __forceinline__ void cp_wait0() {
    asm volatile("cp.async.wait_group 0;" ::: "memory");
}
__device__ __forceinline__ uint32_t h2u(__half2 h) {
    return *reinterpret_cast<uint32_t*>(&h);
}

// ------------------------------------------------- weight frag-pack kernel
__global__ void prep_kernel(const float* __restrict__ W1, const float* __restrict__ W2,
                            const float* __restrict__ W3, const float* __restrict__ W4) {
    int e = blockIdx.x * blockDim.x + threadIdx.x;    // 0 .. 196607
    {
        // L1 weights: W[n(256)][k(768)]
        int n = e / 768, k = e % 768;
        int kc = k >> 6;
        int j  = (k >> 4) & 3;
        int kl = k & 15;
        int p  = kl >> 3;
        int pos = kl & 7;
        int lane = (n & 7) * 4 + (pos >> 1);
        int h = pos & 1;
        int idx = ((((kc * 32 + (n >> 3)) * 4 + j) * 32 + lane) << 2) + p * 2 + h;
        g_B1[0][idx] = __float2half_rn(W1[e]);
        g_B1[1][idx] = __float2half_rn(W3[e]);
    }
    if (e < 128 * 256) {
        // L2 weights: W[n(128)][k(256)]
        int n = e / 256, k = e % 256;
        int j  = k >> 4;
        int kl = k & 15;
        int p  = kl >> 3;
        int pos = kl & 7;
        int lane = (n & 7) * 4 + (pos >> 1);
        int h = pos & 1;
        int idx = ((((n >> 3) * 16 + j) * 32 + lane) << 2) + p * 2 + h;
        g_B2[0][idx] = __float2half_rn(W2[e]);
        g_B2[1][idx] = __float2half_rn(W4[e]);
    }
}

// ----------------------------------------------------------------- main kernel
__global__ void __launch_bounds__(256, 1) fused_kernel(
    const float* __restrict__ X, const float* __restrict__ W5, float* __restrict__ out) {
    extern __shared__ __align__(128) char smem[];
    const uint32_t sb = smem_u32(smem);
    const int tid = threadIdx.x;
    const int w   = tid >> 5;
    const int l   = tid & 31;
    const int lq  = l & 3;

    const long long blk = blockIdx.x;
    const float* Xbase = X + ((blk >> 5) * 4097LL + (blk & 31) * 128LL + 1LL) * 2304LL;

    // chunk c (0..35): slice s=c/12, k-chunk kc=c%12, A32 buffer c&1.
    // slice col offsets: s0->p1(+768), s1->p2(+1536), s2->q(+0)
    auto issue_chunk = [&](int c) {
        int ss = c / 12, kk = c % 12;
        int soff = (ss == 0) ? 768 : (ss == 1) ? 1536 : 0;
        const int row0 = tid >> 4, seg = tid & 15;
        const float* src = Xbase + (long long)row0 * 2304 + soff + kk * 64 + seg * 4;
        uint32_t dst = sb + SM_A32 + (c & 1) * A32_BYTES + row0 * A32_STRIDE + seg * 16;
        #pragma unroll
        for (int i = 0; i < 8; i++)
            cp_async16(dst + i * 16 * A32_STRIDE, src + i * 16 * 2304);
        cp_commit();
    };

    issue_chunk(0);                                    // earliest possible
    if (tid < 128) ((float*)(smem + SM_W5))[tid] = W5[tid];

    // L1 warp tile: 64m x 64n.  L2 warp tile: 32m x 64n.
    const int wm = w >> 2, wq = w & 3;
    const int wm2 = w >> 1, wn2 = w & 1;

    const float* W5s = (const float*)(smem + SM_W5);
    float* parts = (float*)(smem + SM_PART);

    int c = 0;
    for (int s = 0; s < 3; s++) {
        const uint2* B1g = (const uint2*)g_B1[s == 2 ? 1 : 0];
        const uint2* B2g = (const uint2*)g_B2[s == 2 ? 1 : 0];

        // ================= layer 1: acc[4 mf][8 t][4] = Xslice @ W^T =================
        float acc[4][8][4];
        #pragma unroll
        for (int a = 0; a < 4; a++)
            #pragma unroll
            for (int b = 0; b < 8; b++)
                #pragma unroll
                for (int q = 0; q < 4; q++) acc[a][b][q] = 0.f;

        for (int kc = 0; kc < 12; kc++) {
            if (c + 1 < 36) { issue_chunk(c + 1); cp_wait1(); }
            else            { cp_wait0(); }
            __syncthreads();          // chunk c arrived; prev compute done (AF16 free)

            // ---- convert fp32 chunk -> fp16 AF16 (pad-144B rows) ----
            {
                const int r = tid & 127, h = tid >> 7;
                const float4* src = (const float4*)(smem + SM_A32 + (c & 1) * A32_BYTES
                                                    + r * A32_STRIDE + h * 128);
                uint32_t dst = sb + SM_AF16 + r * 144 + h * 64;
                #pragma unroll
                for (int i = 0; i < 8; i++) {
                    float4 v = src[i];
                    uint32_t p0 = h2u(__floats2half2_rn(v.x, v.y));
                    uint32_t p1 = h2u(__floats2half2_rn(v.z, v.w));
                    asm volatile("st.shared.v2.b32 [%0], {%1,%2};"
                                 :: "r"(dst + i * 8), "r"(p0), "r"(p1));
                }
            }
            __syncthreads();

            // ---- compute: 4 k16 steps; B frags from global L2 w/ prefetch ----
            const uint32_t aBase = sb + SM_AF16 + (wm * 64 + (l & 15)) * 144 + (l >> 4) * 16;
            const uint2* bG = B1g + kc * 4096 + wq * 1024 + l;
            uint2 bv[8];
            #pragma unroll
            for (int t = 0; t < 8; t++) bv[t] = bG[t * 128];          // j = 0
            #pragma unroll
            for (int j = 0; j < 4; j++) {
                uint32_t afr[4][4];
                #pragma unroll
                for (int mf = 0; mf < 4; mf++)
                    ldm_x4(afr[mf], aBase + mf * 16 * 144 + j * 32);
                uint2 bn[8];
                if (j < 3) {
                    #pragma unroll
                    for (int t = 0; t < 8; t++) bn[t] = bG[t * 128 + (j + 1) * 32];
                }
                #pragma unroll
                for (int mf = 0; mf < 4; mf++)
                    #pragma unroll
                    for (int t = 0; t < 8; t++)
                        mma16816(acc[mf][t], afr[mf], bv[t].x, bv[t].y);
                if (j < 3) {
                    #pragma unroll
                    for (int t = 0; t < 8; t++) bv[t] = bn[t];
                }
            }
            c++;
        }
        // (next slice's chunk 0 is already in flight -> overlaps the epilogue below)

        // ================= relu -> fp16 -> H1 smem (pad-528B rows) =================
        #pragma unroll
        for (int mf = 0; mf < 4; mf++) {
            #pragma unroll
            for (int t = 0; t < 8; t++) {
                const int r0 = wm * 64 + mf * 16 + (l >> 2);
                const int col = wq * 64 + t * 8 + lq * 2;
                float* cc = acc[mf][t];
                *(uint32_t*)(smem + SM_H1 + r0 * 528 + col * 2) =
                    h2u(__floats2half2_rn(fmaxf(cc[0], 0.f), fmaxf(cc[1], 0.f)));
                *(uint32_t*)(smem + SM_H1 + (r0 + 8) * 528 + col * 2) =
                    h2u(__floats2half2_rn(fmaxf(cc[2], 0.f), fmaxf(cc[3], 0.f)));
            }
        }
        __syncthreads();

        // ================= layer 2: acc2[2 mf][8 t][4] = H1 @ W2^T =================
        float acc2[2][8][4];
        #pragma unroll
        for (int a = 0; a < 2; a++)
            #pragma unroll
            for (int b = 0; b < 8; b++)
                #pragma unroll
                for (int q = 0; q < 4; q++) acc2[a][b][q] = 0.f;

        {
            const uint32_t aBase = sb + SM_H1 + (wm2 * 32 + (l & 15)) * 528 + (l >> 4) * 16;
            const uint2* bG = B2g + wn2 * 4096 + l;
            uint2 bv[8];
            #pragma unroll
            for (int t = 0; t < 8; t++) bv[t] = bG[t * 512];          // j = 0
            #pragma unroll
            for (int j = 0; j < 16; j++) {
                uint32_t afr[2][4];
                #pragma unroll
                for (int mf = 0; mf < 2; mf++)
                    ldm_x4(afr[mf], aBase + mf * 16 * 528 + j * 32);
                uint2 bn[8];
                if (j < 15) {
                    #pragma unroll
                    for (int t = 0; t < 8; t++) bn[t] = bG[t * 512 + (j + 1) * 32];
                }
                #pragma unroll
                for (int t = 0; t < 8; t++)
                    #pragma unroll
                    for (int mf = 0; mf < 2; mf++)
                        mma16816(acc2[mf][t], afr[mf], bv[t].x, bv[t].y);
                if (j < 15) {
                    #pragma unroll
                    for (int t = 0; t < 8; t++) bv[t] = bn[t];
                }
            }
        }
        __syncthreads();   // H1 reads done before next slice's converts reuse nothing,
                           // but needed before D-buffer writes race? (warp-private) —
                           // kept to separate H1 use from next-slice AF16 convert sync.

        // ================= combine via D buffer (pad-272B rows, warp-private) ======
        if (s == 0) {
            #pragma unroll
            for (int mf = 0; mf < 2; mf++)
                #pragma unroll
                for (int t = 0; t < 8; t++) {
                    const int r0 = wm2 * 32 + mf * 16 + (l >> 2);
                    const int col = wn2 * 64 + t * 8 + lq * 2;
                    float* cc = acc2[mf][t];
                    *(uint32_t*)(smem + SM_D + r0 * 272 + col * 2) =
                        h2u(__floats2half2_rn(fmaxf(cc[0], 0.f), fmaxf(cc[1], 0.f)));
                    *(uint32_t*)(smem + SM_D + (r0 + 8) * 272 + col * 2) =
                        h2u(__floats2half2_rn(fmaxf(cc[2], 0.f), fmaxf(cc[3], 0.f)));
                }
        } else if (s == 1) {
            #pragma unroll
            for (int mf = 0; mf < 2; mf++)
                #pragma unroll
                for (int t = 0; t < 8; t++) {
                    const int r0 = wm2 * 32 + mf * 16 + (l >> 2);
                    const int col = wn2 * 64 + t * 8 + lq * 2;
                    float* cc = acc2[mf][t];
                    uint32_t* d0 = (uint32_t*)(smem + SM_D + r0 * 272 + col * 2);
                    uint32_t* d1 = (uint32_t*)(smem + SM_D + (r0 + 8) * 272 + col * 2);
                    float2 fa = __half22float2(*(__half2*)d0);
                    float2 fb = __half22float2(*(__half2*)d1);
                    *d0 = h2u(__floats2half2_rn(fabsf(fa.x - fmaxf(cc[0], 0.f)),
                                                fabsf(fa.y - fmaxf(cc[1], 0.f))));
                    *d1 = h2u(__floats2half2_rn(fabsf(fb.x - fmaxf(cc[2], 0.f)),
                                                fabsf(fb.y - fmaxf(cc[3], 0.f))));
                }
        } else {
            float pd[2][2] = {{0.f, 0.f}, {0.f, 0.f}};
            #pragma unroll
            for (int mf = 0; mf < 2; mf++)
                #pragma unroll
                for (int t = 0; t < 8; t++) {
                    const int r0 = wm2 * 32 + mf * 16 + (l >> 2);
                    const int col = wn2 * 64 + t * 8 + lq * 2;
                    float* cc = acc2[mf][t];
                    float2 da = __half22float2(*(__half2*)(smem + SM_D + r0 * 272 + col * 2));
                    float2 db = __half22float2(*(__half2*)(smem + SM_D + (r0 + 8) * 272 + col * 2));
                    float w0 = W5s[col], w1 = W5s[col + 1];
                    pd[mf][0] += w0 * fmaxf(cc[0], 0.f) * da.x + w1 * fmaxf(cc[1], 0.f) * da.y;
                    pd[mf][1] += w0 * fmaxf(cc[2], 0.f) * db.x + w1 * fmaxf(cc[3], 0.f) * db.y;
                }
            #pragma unroll
            for (int mf = 0; mf < 2; mf++)
                #pragma unroll
                for (int rr = 0; rr < 2; rr++) {
                    float v = pd[mf][rr];
                    v += __shfl_xor_sync(0xFFFFFFFF, v, 1);
                    v += __shfl_xor_sync(0xFFFFFFFF, v, 2);
                    if (lq == 0) {
                        int row = wm2 * 32 + mf * 16 + rr * 8 + (l >> 2);
                        parts[row * 2 + wn2] = v;
                    }
                }
        }
    }

    __syncthreads();
    if (tid < 128) {
        float sum = parts[tid * 2] + parts[tid * 2 + 1];
        out[blk * 128 + tid] = tanhf(fmaxf(sum, 0.f));
    }
}

// ------------------------------------------------------------------- launcher
extern "C" void kernel_launch(void* const* d_in, const int* in_sizes, int n_in,
                              void* d_out, int out_size) {
    const float* X  = (const float*)d_in[0];
    const float* W1 = (const float*)d_in[1];
    const float* W2 = (const float*)d_in[2];
    const float* W3 = (const float*)d_in[3];
    const float* W4 = (const float*)d_in[4];
    const float* W5 = (const float*)d_in[5];
    (void)in_sizes; (void)n_in; (void)out_size;

    cudaFuncSetAttribute(fused_kernel, cudaFuncAttributeMaxDynamicSharedMemorySize, SMEM_BYTES);

    prep_kernel<<<768, 256>>>(W1, W2, W3, W4);
    fused_kernel<<<512, 256, SMEM_BYTES>>>(X, W5, (float*)d_out);
}